// round 14
// baseline (speedup 1.0000x reference)
#include <cuda_runtime.h>
#include <cuda_fp16.h>
#include <math.h>
#include <stdint.h>

// Problem constants
#define B_ 512
#define T_ 256
#define H_ 512
#define E_ 10
#define V_ 10000
#define C_ 10
#define NGATE 4
#define N_TOT (NGATE * H_)   // 2048; layout n = 4*j + gate (gates interleaved)

#define NBLK 128             // persistent blocks: 1/SM guaranteed by smem
#define NT 1024              // 32 warps -> 8 warps/SMSP

// ---------------------------------------------------------------------------
// Device globals (no allocations allowed)
// ---------------------------------------------------------------------------
__device__ float g_c[B_ * H_];
__device__ __half g_hh[2][B_ * H_];    // ping-pong recurrent state (fp16)
__device__ __half g_Wt[N_TOT * H_];    // W^T fp16: [n=4j+g][k]
__device__ float g_xef[T_ * B_ * 16];  // pre-gathered emb[x], padded to 16
__device__ unsigned g_cnt;
__device__ volatile unsigned g_gen;

// ---------------------------------------------------------------------------
// One-time preps
// ---------------------------------------------------------------------------
__global__ void prep_weights_kernel(
    const float* __restrict__ Wgh, const float* __restrict__ Wih,
    const float* __restrict__ Wfh, const float* __restrict__ Woh)
{
    int idx = blockIdx.x * 256 + threadIdx.x;   // over 2048*512
    int n = idx >> 9;
    int k = idx & 511;
    int g = n & 3;
    int j = n >> 2;
    const float* const W[4] = {Wgh, Wih, Wfh, Woh};
    g_Wt[n * H_ + k] = __float2half(W[g][k * H_ + j]);
}

__global__ void prep_xe_kernel(const int* __restrict__ x,
                               const float* __restrict__ emb) {
    int idx = blockIdx.x * 256 + threadIdx.x;   // over T*B*16 = 2M
    int t = idx >> 13;           // B*16 = 8192
    int b = (idx >> 4) & (B_ - 1);
    int e = idx & 15;
    float v = 0.0f;
    if (e < E_) {
        int tok = x[b * T_ + t];
        tok = min(max(tok, 0), V_ - 1);
        v = emb[tok * E_ + e];
    }
    g_xef[idx] = v;
}

__global__ void init_state_kernel() {
    int i = blockIdx.x * blockDim.x + threadIdx.x;
    if (i < B_ * H_) {
        g_c[i] = 0.0f;
        g_hh[0][i] = __float2half(0.0f);
    }
    if (i == 0) { g_cnt = 0u; g_gen = 0u; }
}

// ---------------------------------------------------------------------------
// PTX helpers
// ---------------------------------------------------------------------------
__device__ __forceinline__ void cp16(void* smem_dst, const void* gmem_src) {
    uint32_t s = (uint32_t)__cvta_generic_to_shared(smem_dst);
    asm volatile("cp.async.cg.shared.global [%0], [%1], 16;" :: "r"(s), "l"(gmem_src));
}

__device__ __forceinline__ void ldm_x4(uint32_t r[4], uint32_t addr) {
    asm volatile("ldmatrix.sync.aligned.m8n8.x4.shared.b16 {%0,%1,%2,%3}, [%4];"
                 : "=r"(r[0]), "=r"(r[1]), "=r"(r[2]), "=r"(r[3]) : "r"(addr));
}

__device__ __forceinline__ void mma_f16(
    float c[4], const uint32_t a[4], uint32_t b0, uint32_t b1)
{
    asm volatile(
        "mma.sync.aligned.m16n8k16.row.col.f32.f16.f16.f32 "
        "{%0,%1,%2,%3}, {%4,%5,%6,%7}, {%8,%9}, {%0,%1,%2,%3};"
        : "+f"(c[0]), "+f"(c[1]), "+f"(c[2]), "+f"(c[3])
        : "r"(a[0]), "r"(a[1]), "r"(a[2]), "r"(a[3]), "r"(b0), "r"(b1));
}

// ---------------------------------------------------------------------------
// smem layout (dynamic):
//   W tile    : 64 n-rows x pitch 520 fp16 (1040B: 260w%32=4, conflict-free)
//   A stages  : 3 x [128 rows x 72] fp16  (k-chunk 64; 144B stride)
//   z (alias over A stages), xe, xw, bias
// ---------------------------------------------------------------------------
#define WPITCH 520
#define W_BYTES (64 * WPITCH * 2)            // 66560
#define APAD 72
#define A_ST_BYTES (128 * APAD * 2)          // 18432
#define A_OFF2 W_BYTES
#define Z_OFF A_OFF2                         // alias: z (34816B) < 3 stages
#define ZP 68
#define XE_OFF (A_OFF2 + 3 * A_ST_BYTES)     // 121856
#define XW_OFF (XE_OFF + 128 * 16 * 4)       // 130048
#define BI_OFF (XW_OFF + NGATE * E_ * 16 * 4)// 132608
#define SMEM_T (BI_OFF + 64 * 4)             // 132864

__global__ void __launch_bounds__(NT, 1) lstm_persistent(
    const float* __restrict__ Wgx, const float* __restrict__ Wix,
    const float* __restrict__ Wfx, const float* __restrict__ Wox,
    const float* __restrict__ bg, const float* __restrict__ bi,
    const float* __restrict__ bf_, const float* __restrict__ bo)
{
    extern __shared__ __align__(16) char sm[];
    const int tid = threadIdx.x;
    const int bid = blockIdx.x;
    const int nt = bid & 31;
    const int mt = bid >> 5;
    const int bn = nt * 64;      // global col base (n = 4j+g)
    const int bj = nt * 16;      // j base
    const int bb = mt * 128;     // batch base
    const int w = tid >> 5;
    const int lane = tid & 31;
    const int gid = lane >> 2;
    const int tig = lane & 3;
    const int wm = (w >> 2) * 16;    // 8 m-groups of 16 rows
    const int wn = (w & 3) * 16;     // 4 n-groups of 16 cols

    const uint32_t SBase = (uint32_t)__cvta_generic_to_shared(sm);
    float* const z_s    = (float*)(sm + Z_OFF);
    float* const xe_s   = (float*)(sm + XE_OFF);
    float* const xw_s   = (float*)(sm + XW_OFF);
    float* const bias_s = (float*)(sm + BI_OFF);

    // ldmatrix per-lane offsets
    const uint32_t w_frag = SBase +
        ((wn + ((lane >> 4) & 1) * 8 + (lane & 7)) * WPITCH + ((lane >> 3) & 1) * 8) * 2;
    const uint32_t a_rel =
        ((wm + ((lane >> 3) & 1) * 8 + (lane & 7)) * APAD + ((lane >> 4) & 1) * 8) * 2;

    // ---- one-time prologue: W tile -> smem, xw/bias -> smem ----
    #pragma unroll
    for (int i = 0; i < 4; i++) {                    // 4096 segs of 16B
        int seg = tid + i * NT;
        int row = seg >> 6, ko = seg & 63;
        cp16(sm + row * (WPITCH * 2) + ko * 16, &g_Wt[(bn + row) * H_ + ko * 8]);
    }
    asm volatile("cp.async.commit_group;");
    {
        const float* const Wx[4] = {Wgx, Wix, Wfx, Wox};
        for (int i = tid; i < NGATE * E_ * 16; i += NT) {
            int g = i / (E_ * 16), rem = i % (E_ * 16);
            int e = rem / 16, jl = rem % 16;
            xw_s[i] = Wx[g][e * H_ + bj + jl];
        }
        const float* const bptr[4] = {bg, bi, bf_, bo};
        if (tid < 64) bias_s[tid] = bptr[tid >> 4][bj + (tid & 15)];
    }
    asm volatile("cp.async.wait_group 0;" ::: "memory");
    __syncthreads();

    // ---- time loop ----
    #pragma unroll 1
    for (int t = 0; t < T_; t++) {
        const int src = t & 1;
        const __half* __restrict__ hh = g_hh[src];
        __half* __restrict__ hh_out = g_hh[src ^ 1];

        auto load_chunk = [&](int stage, int k0) {
            char* sb = sm + A_OFF2 + stage * A_ST_BYTES;
            // 128r * 64k fp16 = 16KB = 1024 segs -> 1 per thread
            int r = tid >> 3, ko = tid & 7;
            cp16(sb + r * (APAD * 2) + ko * 16, &hh[(bb + r) * H_ + k0 + ko * 8]);
            asm volatile("cp.async.commit_group;");
        };

        // xe for this step (rides in chunk 0's group)
        if (tid < 512) {
            int r = tid >> 2, q = (tid & 3) * 4;
            cp16(sm + XE_OFF + (r * 16 + q) * 4,
                 &g_xef[(t * B_ + bb + r) * 16 + q]);
        }
        load_chunk(0, 0);
        load_chunk(1, 64);

        float acc[2][4];
        #pragma unroll
        for (int i = 0; i < 2; i++)
            #pragma unroll
            for (int v = 0; v < 4; v++) acc[i][v] = 0.0f;

        #pragma unroll 1
        for (int kt = 0; kt < 8; kt++) {
            if (kt < 6) asm volatile("cp.async.wait_group 1;" ::: "memory");
            else        asm volatile("cp.async.wait_group 0;" ::: "memory");
            __syncthreads();
            if (kt + 2 < 8) load_chunk((kt + 2) % 3, (kt + 2) * 64);

            const uint32_t sb = SBase + A_OFF2 + (kt % 3) * A_ST_BYTES;
            #pragma unroll
            for (int kk = 0; kk < 4; kk++) {
                uint32_t Av[4], Bv[4];
                ldm_x4(Av, sb + a_rel + kk * 32);
                ldm_x4(Bv, w_frag + (kt * 64 + kk * 16) * 2);
                mma_f16(acc[0], Av, Bv[0], Bv[1]);
                mma_f16(acc[1], Av, Bv[2], Bv[3]);
            }
        }
        __syncthreads();   // all warps done with A stages before z aliases

        // spill accs to z_s (aliased over dead A stages)
        #pragma unroll
        for (int nf = 0; nf < 2; nf++) {
            const int col = wn + nf * 8 + 2 * tig;
            *(float2*)&z_s[(wm + gid) * ZP + col] =
                make_float2(acc[nf][0], acc[nf][1]);
            *(float2*)&z_s[(wm + gid + 8) * ZP + col] =
                make_float2(acc[nf][2], acc[nf][3]);
        }
        __syncthreads();

        // pointwise: 128 rows x 16 j = 2048 units / 1024 threads = 2 reps
        #pragma unroll
        for (int rep = 0; rep < 2; rep++) {
            const int elem = tid + rep * NT;
            const int r = elem >> 4, jl = elem & 15;
            const int gr = bb + r, gj = bj + jl;

            float4 zv = *(const float4*)&z_s[r * ZP + 4 * jl];
            float zg = zv.x + bias_s[jl];
            float zi = zv.y + bias_s[16 + jl];
            float zf = zv.z + bias_s[32 + jl];
            float zo = zv.w + bias_s[48 + jl];

            #pragma unroll
            for (int e = 0; e < E_; e++) {
                float xv = xe_s[r * 16 + e];
                zg += xv * xw_s[(0 * E_ + e) * 16 + jl];
                zi += xv * xw_s[(1 * E_ + e) * 16 + jl];
                zf += xv * xw_s[(2 * E_ + e) * 16 + jl];
                zo += xv * xw_s[(3 * E_ + e) * 16 + jl];
            }

            float gg = tanhf(zg);
            float ii = 1.0f / (1.0f + __expf(-zi));
            float ff = 1.0f / (1.0f + __expf(-zf));
            float oo = 1.0f / (1.0f + __expf(-zo));

            float cn = gg * ii + g_c[gr * H_ + gj] * ff;
            float hn = tanhf(cn) * oo;
            g_c[gr * H_ + gj] = cn;
            hh_out[gr * H_ + gj] = __float2half(hn);
        }

        // ---- grid barrier: atomic arrive + generation release ----
        __syncthreads();
        if (tid == 0) {
            __threadfence();
            unsigned prev = atomicAdd(&g_cnt, 1u);
            if (prev == NBLK - 1) {
                g_cnt = 0u;
                __threadfence();
                g_gen = (unsigned)(t + 1);
            }
        }
        if (tid == 0) {
            while (g_gen < (unsigned)(t + 1)) { }
            __threadfence();
        }
        __syncthreads();
    }
}

// ---------------------------------------------------------------------------
// Final projection: h from fp16 buffer 0 (after t=255).
// ---------------------------------------------------------------------------
__global__ void proj_kernel(const float* __restrict__ Wph,
                            const float* __restrict__ bp, float* __restrict__ out) {
    int i = blockIdx.x * blockDim.x + threadIdx.x;
    if (i >= B_ * C_) return;
    int b = i / C_;
    int c = i % C_;
    float acc = bp[c];
    #pragma unroll 8
    for (int k = 0; k < H_; k++) {
        acc += __half2float(g_hh[0][b * H_ + k]) * Wph[k * C_ + c];
    }
    out[i] = acc;
}

// ---------------------------------------------------------------------------
// Launch sequence (graph-capturable, single stream)
// ---------------------------------------------------------------------------
extern "C" void kernel_launch(void* const* d_in, const int* in_sizes, int n_in,
                              void* d_out, int out_size) {
    const int* x        = (const int*)d_in[0];       // int32 (JAX downcasts int64)
    const float* emb    = (const float*)d_in[1];
    const float* Wgx    = (const float*)d_in[2];
    const float* Wgh    = (const float*)d_in[3];
    const float* bg     = (const float*)d_in[4];
    const float* Wix    = (const float*)d_in[5];
    const float* Wih    = (const float*)d_in[6];
    const float* bi     = (const float*)d_in[7];
    const float* Wfx    = (const float*)d_in[8];
    const float* Wfh    = (const float*)d_in[9];
    const float* bf_    = (const float*)d_in[10];
    const float* Wox    = (const float*)d_in[11];
    const float* Woh    = (const float*)d_in[12];
    const float* bo     = (const float*)d_in[13];
    const float* Wph    = (const float*)d_in[14];
    const float* bp     = (const float*)d_in[15];
    float* out          = (float*)d_out;

    static bool attr_set = false;
    if (!attr_set) {
        cudaFuncSetAttribute(lstm_persistent,
                             cudaFuncAttributeMaxDynamicSharedMemorySize,
                             SMEM_T);
        attr_set = true;
    }

    prep_weights_kernel<<<(N_TOT * H_) / 256, 256>>>(Wgh, Wih, Wfh, Woh);
    prep_xe_kernel<<<(T_ * B_ * 16) / 256, 256>>>(x, emb);
    init_state_kernel<<<(B_ * H_ + 255) / 256, 256>>>();

    lstm_persistent<<<NBLK, NT, SMEM_T>>>(
        Wgx, Wix, Wfx, Wox, bg, bi, bf_, bo);

    proj_kernel<<<(B_ * C_ + 255) / 256, 256>>>(Wph, bp, out);
}

// round 15
// speedup vs baseline: 1.0684x; 1.0684x over previous
#include <cuda_runtime.h>
#include <cuda_fp16.h>
#include <math.h>
#include <stdint.h>

// Problem constants
#define B_ 512
#define T_ 256
#define H_ 512
#define E_ 10
#define V_ 10000
#define C_ 10
#define NGATE 4
#define N_TOT (NGATE * H_)   // 2048; layout n = 4*j + gate (gates interleaved)

#define NBLK 128             // persistent blocks: 1/SM guaranteed by smem
#define NT 1024              // 32 warps -> 8 warps/SMSP

// ---------------------------------------------------------------------------
// Device globals (no allocations allowed)
// ---------------------------------------------------------------------------
__device__ float g_c[B_ * H_];
__device__ __half g_hh[2][B_ * H_];    // ping-pong recurrent state (fp16)
__device__ __half g_Wt[N_TOT * H_];    // W^T fp16: [n=4j+g][k]
__device__ float g_xef[T_ * B_ * 16];  // pre-gathered emb[x], padded to 16
// per-mt-group barriers (4 groups x 32 blocks), padded to separate lines
__device__ unsigned g_cnt4[4 * 32];
__device__ volatile unsigned g_gen4[4 * 32];

// ---------------------------------------------------------------------------
// One-time preps
// ---------------------------------------------------------------------------
__global__ void prep_weights_kernel(
    const float* __restrict__ Wgh, const float* __restrict__ Wih,
    const float* __restrict__ Wfh, const float* __restrict__ Woh)
{
    int idx = blockIdx.x * 256 + threadIdx.x;   // over 2048*512
    int n = idx >> 9;
    int k = idx & 511;
    int g = n & 3;
    int j = n >> 2;
    const float* const W[4] = {Wgh, Wih, Wfh, Woh};
    g_Wt[n * H_ + k] = __float2half(W[g][k * H_ + j]);
}

__global__ void prep_xe_kernel(const int* __restrict__ x,
                               const float* __restrict__ emb) {
    int idx = blockIdx.x * 256 + threadIdx.x;   // over T*B*16 = 2M
    int t = idx >> 13;           // B*16 = 8192
    int b = (idx >> 4) & (B_ - 1);
    int e = idx & 15;
    float v = 0.0f;
    if (e < E_) {
        int tok = x[b * T_ + t];
        tok = min(max(tok, 0), V_ - 1);
        v = emb[tok * E_ + e];
    }
    g_xef[idx] = v;
}

__global__ void init_state_kernel() {
    int i = blockIdx.x * blockDim.x + threadIdx.x;
    if (i < B_ * H_) {
        g_c[i] = 0.0f;
        g_hh[0][i] = __float2half(0.0f);
    }
    if (i < 4 * 32) { g_cnt4[i] = 0u; g_gen4[i] = 0u; }
}

// ---------------------------------------------------------------------------
// PTX helpers
// ---------------------------------------------------------------------------
__device__ __forceinline__ void cp16(void* smem_dst, const void* gmem_src) {
    uint32_t s = (uint32_t)__cvta_generic_to_shared(smem_dst);
    asm volatile("cp.async.cg.shared.global [%0], [%1], 16;" :: "r"(s), "l"(gmem_src));
}

__device__ __forceinline__ void ldm_x4(uint32_t r[4], uint32_t addr) {
    asm volatile("ldmatrix.sync.aligned.m8n8.x4.shared.b16 {%0,%1,%2,%3}, [%4];"
                 : "=r"(r[0]), "=r"(r[1]), "=r"(r[2]), "=r"(r[3]) : "r"(addr));
}

__device__ __forceinline__ void mma_f16(
    float c[4], const uint32_t a[4], uint32_t b0, uint32_t b1)
{
    asm volatile(
        "mma.sync.aligned.m16n8k16.row.col.f32.f16.f16.f32 "
        "{%0,%1,%2,%3}, {%4,%5,%6,%7}, {%8,%9}, {%0,%1,%2,%3};"
        : "+f"(c[0]), "+f"(c[1]), "+f"(c[2]), "+f"(c[3])
        : "r"(a[0]), "r"(a[1]), "r"(a[2]), "r"(a[3]), "r"(b0), "r"(b1));
}

// saturation-safe fast activations (inf-safe at both rails)
__device__ __forceinline__ float fast_tanh(float x) {
    return 1.0f - __fdividef(2.0f, __expf(2.0f * x) + 1.0f);
}
__device__ __forceinline__ float fast_sig(float x) {
    return __fdividef(1.0f, 1.0f + __expf(-x));
}

// ---------------------------------------------------------------------------
// smem layout (dynamic):
//   W tile    : 64 n-rows x pitch 520 fp16 (1040B: conflict-free ldmatrix)
//   A stages  : 3 x [128 rows x 72] fp16  (k-chunk 64; 144B stride)
//   z (alias over A stages), xe, xw, bias
// ---------------------------------------------------------------------------
#define WPITCH 520
#define W_BYTES (64 * WPITCH * 2)            // 66560
#define APAD 72
#define A_ST_BYTES (128 * APAD * 2)          // 18432
#define A_OFF2 W_BYTES
#define Z_OFF A_OFF2                         // alias: z (34816B) < 3 stages
#define ZP 68
#define XE_OFF (A_OFF2 + 3 * A_ST_BYTES)     // 121856
#define XW_OFF (XE_OFF + 128 * 16 * 4)       // 130048
#define BI_OFF (XW_OFF + NGATE * E_ * 16 * 4)// 132608
#define SMEM_T (BI_OFF + 64 * 4)             // 132864

__global__ void __launch_bounds__(NT, 1) lstm_persistent(
    const float* __restrict__ Wgx, const float* __restrict__ Wix,
    const float* __restrict__ Wfx, const float* __restrict__ Wox,
    const float* __restrict__ bg, const float* __restrict__ bi,
    const float* __restrict__ bf_, const float* __restrict__ bo)
{
    extern __shared__ __align__(16) char sm[];
    const int tid = threadIdx.x;
    const int bid = blockIdx.x;
    const int nt = bid & 31;
    const int mt = bid >> 5;
    const int bn = nt * 64;      // global col base (n = 4j+g)
    const int bj = nt * 16;      // j base
    const int bb = mt * 128;     // batch base
    const int w = tid >> 5;
    const int lane = tid & 31;
    const int gid = lane >> 2;
    const int tig = lane & 3;
    const int wm = (w >> 2) * 16;    // 8 m-groups of 16 rows
    const int wn = (w & 3) * 16;     // 4 n-groups of 16 cols

    const uint32_t SBase = (uint32_t)__cvta_generic_to_shared(sm);
    float* const z_s    = (float*)(sm + Z_OFF);
    float* const xe_s   = (float*)(sm + XE_OFF);
    float* const xw_s   = (float*)(sm + XW_OFF);
    float* const bias_s = (float*)(sm + BI_OFF);

    // ldmatrix per-lane offsets
    const uint32_t w_frag = SBase +
        ((wn + ((lane >> 4) & 1) * 8 + (lane & 7)) * WPITCH + ((lane >> 3) & 1) * 8) * 2;
    const uint32_t a_rel =
        ((wm + ((lane >> 3) & 1) * 8 + (lane & 7)) * APAD + ((lane >> 4) & 1) * 8) * 2;

    // per-mt-group barrier slots
    unsigned* const cnt_p = &g_cnt4[mt * 32];
    volatile unsigned* const gen_p = &g_gen4[mt * 32];

    // ---- one-time prologue: W tile -> smem, xw/bias -> smem ----
    #pragma unroll
    for (int i = 0; i < 4; i++) {                    // 4096 segs of 16B
        int seg = tid + i * NT;
        int row = seg >> 6, ko = seg & 63;
        cp16(sm + row * (WPITCH * 2) + ko * 16, &g_Wt[(bn + row) * H_ + ko * 8]);
    }
    asm volatile("cp.async.commit_group;");
    {
        const float* const Wx[4] = {Wgx, Wix, Wfx, Wox};
        for (int i = tid; i < NGATE * E_ * 16; i += NT) {
            int g = i / (E_ * 16), rem = i % (E_ * 16);
            int e = rem / 16, jl = rem % 16;
            xw_s[i] = Wx[g][e * H_ + bj + jl];
        }
        const float* const bptr[4] = {bg, bi, bf_, bo};
        if (tid < 64) bias_s[tid] = bptr[tid >> 4][bj + (tid & 15)];
    }
    asm volatile("cp.async.wait_group 0;" ::: "memory");
    __syncthreads();

    // ---- time loop ----
    #pragma unroll 1
    for (int t = 0; t < T_; t++) {
        const int src = t & 1;
        const __half* __restrict__ hh = g_hh[src];
        __half* __restrict__ hh_out = g_hh[src ^ 1];

        auto load_chunk = [&](int stage, int k0) {
            char* sb = sm + A_OFF2 + stage * A_ST_BYTES;
            // 128r * 64k fp16 = 16KB = 1024 segs -> 1 per thread
            int r = tid >> 3, ko = tid & 7;
            cp16(sb + r * (APAD * 2) + ko * 16, &hh[(bb + r) * H_ + k0 + ko * 8]);
            asm volatile("cp.async.commit_group;");
        };

        // xe for this step (rides in chunk 0's group)
        if (tid < 512) {
            int r = tid >> 2, q = (tid & 3) * 4;
            cp16(sm + XE_OFF + (r * 16 + q) * 4,
                 &g_xef[(t * B_ + bb + r) * 16 + q]);
        }
        load_chunk(0, 0);
        load_chunk(1, 64);

        float acc[2][4];
        #pragma unroll
        for (int i = 0; i < 2; i++)
            #pragma unroll
            for (int v = 0; v < 4; v++) acc[i][v] = 0.0f;

        #pragma unroll 1
        for (int kt = 0; kt < 8; kt++) {
            if (kt < 6) asm volatile("cp.async.wait_group 1;" ::: "memory");
            else        asm volatile("cp.async.wait_group 0;" ::: "memory");
            __syncthreads();
            if (kt + 2 < 8) load_chunk((kt + 2) % 3, (kt + 2) * 64);

            const uint32_t sb = SBase + A_OFF2 + (kt % 3) * A_ST_BYTES;
            #pragma unroll
            for (int kk = 0; kk < 4; kk++) {
                uint32_t Av[4], Bv[4];
                ldm_x4(Av, sb + a_rel + kk * 32);
                ldm_x4(Bv, w_frag + (kt * 64 + kk * 16) * 2);
                mma_f16(acc[0], Av, Bv[0], Bv[1]);
                mma_f16(acc[1], Av, Bv[2], Bv[3]);
            }
        }
        __syncthreads();   // all warps done with A stages before z aliases

        // spill accs to z_s (aliased over dead A stages)
        #pragma unroll
        for (int nf = 0; nf < 2; nf++) {
            const int col = wn + nf * 8 + 2 * tig;
            *(float2*)&z_s[(wm + gid) * ZP + col] =
                make_float2(acc[nf][0], acc[nf][1]);
            *(float2*)&z_s[(wm + gid + 8) * ZP + col] =
                make_float2(acc[nf][2], acc[nf][3]);
        }
        __syncthreads();

        // pointwise: 128 rows x 16 j = 2048 units / 1024 threads = 2 reps
        #pragma unroll
        for (int rep = 0; rep < 2; rep++) {
            const int elem = tid + rep * NT;
            const int r = elem >> 4, jl = elem & 15;
            const int gr = bb + r, gj = bj + jl;

            float4 zv = *(const float4*)&z_s[r * ZP + 4 * jl];
            float zg = zv.x + bias_s[jl];
            float zi = zv.y + bias_s[16 + jl];
            float zf = zv.z + bias_s[32 + jl];
            float zo = zv.w + bias_s[48 + jl];

            #pragma unroll
            for (int e = 0; e < E_; e++) {
                float xv = xe_s[r * 16 + e];
                zg += xv * xw_s[(0 * E_ + e) * 16 + jl];
                zi += xv * xw_s[(1 * E_ + e) * 16 + jl];
                zf += xv * xw_s[(2 * E_ + e) * 16 + jl];
                zo += xv * xw_s[(3 * E_ + e) * 16 + jl];
            }

            float gg = fast_tanh(zg);
            float ii = fast_sig(zi);
            float ff = fast_sig(zf);
            float oo = fast_sig(zo);

            float cn = gg * ii + g_c[gr * H_ + gj] * ff;
            float hn = fast_tanh(cn) * oo;
            g_c[gr * H_ + gj] = cn;
            hh_out[gr * H_ + gj] = __float2half(hn);
        }

        // ---- per-mt-group barrier (32 blocks): arrive + generation ----
        __syncthreads();
        if (tid == 0) {
            __threadfence();
            unsigned prev = atomicAdd(cnt_p, 1u);
            if (prev == 31u) {
                *cnt_p = 0u;
                __threadfence();
                *gen_p = (unsigned)(t + 1);
            }
            while (*gen_p < (unsigned)(t + 1)) { }
            __threadfence();
        }
        __syncthreads();
    }
}

// ---------------------------------------------------------------------------
// Final projection: h from fp16 buffer 0 (after t=255).
// ---------------------------------------------------------------------------
__global__ void proj_kernel(const float* __restrict__ Wph,
                            const float* __restrict__ bp, float* __restrict__ out) {
    int i = blockIdx.x * blockDim.x + threadIdx.x;
    if (i >= B_ * C_) return;
    int b = i / C_;
    int c = i % C_;
    float acc = bp[c];
    #pragma unroll 8
    for (int k = 0; k < H_; k++) {
        acc += __half2float(g_hh[0][b * H_ + k]) * Wph[k * C_ + c];
    }
    out[i] = acc;
}

// ---------------------------------------------------------------------------
// Launch sequence (graph-capturable, single stream)
// ---------------------------------------------------------------------------
extern "C" void kernel_launch(void* const* d_in, const int* in_sizes, int n_in,
                              void* d_out, int out_size) {
    const int* x        = (const int*)d_in[0];       // int32 (JAX downcasts int64)
    const float* emb    = (const float*)d_in[1];
    const float* Wgx    = (const float*)d_in[2];
    const float* Wgh    = (const float*)d_in[3];
    const float* bg     = (const float*)d_in[4];
    const float* Wix    = (const float*)d_in[5];
    const float* Wih    = (const float*)d_in[6];
    const float* bi     = (const float*)d_in[7];
    const float* Wfx    = (const float*)d_in[8];
    const float* Wfh    = (const float*)d_in[9];
    const float* bf_    = (const float*)d_in[10];
    const float* Wox    = (const float*)d_in[11];
    const float* Woh    = (const float*)d_in[12];
    const float* bo     = (const float*)d_in[13];
    const float* Wph    = (const float*)d_in[14];
    const float* bp     = (const float*)d_in[15];
    float* out          = (float*)d_out;

    static bool attr_set = false;
    if (!attr_set) {
        cudaFuncSetAttribute(lstm_persistent,
                             cudaFuncAttributeMaxDynamicSharedMemorySize,
                             SMEM_T);
        attr_set = true;
    }

    prep_weights_kernel<<<(N_TOT * H_) / 256, 256>>>(Wgh, Wih, Wfh, Woh);
    prep_xe_kernel<<<(T_ * B_ * 16) / 256, 256>>>(x, emb);
    init_state_kernel<<<(B_ * H_ + 255) / 256, 256>>>();

    lstm_persistent<<<NBLK, NT, SMEM_T>>>(
        Wgx, Wix, Wfx, Wox, bg, bi, bf_, bo);

    proj_kernel<<<(B_ * C_ + 255) / 256, 256>>>(Wph, bp, out);
}